// round 15
// baseline (speedup 1.0000x reference)
#include <cuda_runtime.h>
#include <cuda_bf16.h>
#include <cstdint>
#include <math.h>

// ---------------------------------------------------------------------------
// Problem constants
// ---------------------------------------------------------------------------
#define BATCH   65536
#define TSTEPS  25
#define H1      1024
#define H2      512
#define DIN     64
#define BETA    0.95f

// ---------------------------------------------------------------------------
// Device scratch — total ~720 MB (must stay < ~2 GB: aarch64 .bss reloc range)
// ---------------------------------------------------------------------------
__device__ float          g_cur1[(size_t)BATCH * H1];                    // 268 MB
__device__ uint32_t       g_spk1b[(size_t)TSTEPS * BATCH * (H1 / 32)];   // 210 MB (bit k)
__device__ uint32_t       g_spk2b[(size_t)TSTEPS * BATCH * (H2 / 32)];   // 105 MB (bit n)
__device__ float          g_mem2[(size_t)BATCH * H2];                    // 134 MB
__device__ __nv_bfloat16  g_w2hi[(size_t)H2 * H1];                       // [n][k]
__device__ __nv_bfloat16  g_w2lo[(size_t)H2 * H1];                       // [n][k]

// ---------------------------------------------------------------------------
// PTX helpers — sm_80+ only (toolchain lowers via compute_103 base target;
// tcgen05 / 'a'-features unavailable)
// ---------------------------------------------------------------------------
__device__ __forceinline__ uint32_t smem_to_u32(const void* p) {
    uint32_t a;
    asm("{ .reg .u64 t; cvta.to.shared.u64 t, %1; cvt.u32.u64 %0, t; }" : "=r"(a) : "l"(p));
    return a;
}

#define CP_ASYNC16(dst_u32, src_ptr) do {                                        \
    unsigned long long _g = __cvta_generic_to_global((const void*)(src_ptr));    \
    asm volatile("cp.async.cg.shared.global [%0], [%1], 16;"                     \
                 :: "r"(dst_u32), "l"(_g) : "memory");                           \
} while (0)
#define CP_COMMIT()  asm volatile("cp.async.commit_group;" ::: "memory")
#define CP_WAIT1()   asm volatile("cp.async.wait_group 1;" ::: "memory")
#define CP_WAIT0()   asm volatile("cp.async.wait_group 0;" ::: "memory")

#define LDMX4(r, addr)                                                           \
    asm volatile("ldmatrix.sync.aligned.m8n8.x4.shared.b16 {%0,%1,%2,%3}, [%4];" \
        : "=r"((r)[0]), "=r"((r)[1]), "=r"((r)[2]), "=r"((r)[3]) : "r"(addr))

#define MMA_BF16(d, a, b0_, b1_)                                                 \
    asm volatile("mma.sync.aligned.m16n8k16.row.col.f32.bf16.bf16.f32 "          \
        "{%0,%1,%2,%3}, {%4,%5,%6,%7}, {%8,%9}, {%0,%1,%2,%3};"                  \
        : "+f"((d)[0]), "+f"((d)[1]), "+f"((d)[2]), "+f"((d)[3])                 \
        : "r"((a)[0]), "r"((a)[1]), "r"((a)[2]), "r"((a)[3]), "r"(b0_), "r"(b1_))

// Exact (non-fma-contracted) LIF step matching jnp:  m = B*m + c - r
__device__ __forceinline__ void lif_step(float& m, float c, float& spk) {
    float r = (m > 1.0f) ? 1.0f : 0.0f;
    m = __fsub_rn(__fadd_rn(__fmul_rn(BETA, m), c), r);
    spk = (m > 1.0f) ? 1.0f : 0.0f;
}

// ---------------------------------------------------------------------------
// Kernel P: two-limb bf16 split of W2, transposed to [n][k] (B operand).
// spikes are {0,1} -> products with each limb are exact; hi+lo ~= fp32 W2.
// ---------------------------------------------------------------------------
__global__ void __launch_bounds__(256) k_prep_w2(const float* __restrict__ W2) {
    int idx = blockIdx.x * 256 + threadIdx.x;            // < 1024*512
    int k = idx >> 9;
    int n = idx & 511;
    float w = W2[(size_t)k * H2 + n];
    __nv_bfloat16 hi = __float2bfloat16(w);
    float r = w - __bfloat162float(hi);                  // exact residual
    g_w2hi[(size_t)n * H1 + k] = hi;
    g_w2lo[(size_t)n * H1 + k] = __float2bfloat16(r);
}

// ---------------------------------------------------------------------------
// Kernel 0: cur1 = x@W1 + b1 (fp32 SIMT GEMM, K=64). Tile 64x64, thread 4x4.
// ---------------------------------------------------------------------------
__global__ void __launch_bounds__(256) k0_gemm1(const float* __restrict__ x,
                                                const float* __restrict__ W1,
                                                const float* __restrict__ b1) {
    __shared__ float xs[64][65];
    __shared__ float ws[64][64];
    int hb = blockIdx.x & 15, bb = blockIdx.x >> 4;
    int b0 = bb * 64, h0 = hb * 64;
    int tid = threadIdx.x;

    for (int i = tid; i < 4096; i += 256) {
        int r = i >> 6, c = i & 63;
        xs[r][c] = x[(size_t)(b0 + r) * DIN + c];
        ws[r][c] = W1[(size_t)r * H1 + h0 + c];
    }
    __syncthreads();

    int tx = tid & 15, ty = tid >> 4;
    float acc[4][4] = {};
    #pragma unroll 8
    for (int k = 0; k < 64; k++) {
        float a0 = xs[ty * 4 + 0][k], a1 = xs[ty * 4 + 1][k];
        float a2 = xs[ty * 4 + 2][k], a3 = xs[ty * 4 + 3][k];
        float w0 = ws[k][tx * 4 + 0], w1 = ws[k][tx * 4 + 1];
        float w2 = ws[k][tx * 4 + 2], w3 = ws[k][tx * 4 + 3];
        acc[0][0] += a0 * w0; acc[0][1] += a0 * w1; acc[0][2] += a0 * w2; acc[0][3] += a0 * w3;
        acc[1][0] += a1 * w0; acc[1][1] += a1 * w1; acc[1][2] += a1 * w2; acc[1][3] += a1 * w3;
        acc[2][0] += a2 * w0; acc[2][1] += a2 * w1; acc[2][2] += a2 * w2; acc[2][3] += a2 * w3;
        acc[3][0] += a3 * w0; acc[3][1] += a3 * w1; acc[3][2] += a3 * w2; acc[3][3] += a3 * w3;
    }
    float c0 = b1[h0 + tx * 4 + 0], c1 = b1[h0 + tx * 4 + 1];
    float c2 = b1[h0 + tx * 4 + 2], c3 = b1[h0 + tx * 4 + 3];
    #pragma unroll
    for (int i = 0; i < 4; i++) {
        float4 v;
        v.x = acc[i][0] + c0; v.y = acc[i][1] + c1;
        v.z = acc[i][2] + c2; v.w = acc[i][3] + c3;
        *(float4*)(g_cur1 + (size_t)(b0 + ty * 4 + i) * H1 + h0 + tx * 4) = v;
    }
}

// ---------------------------------------------------------------------------
// Kernel 1: layer-1 LIF (cur1 static in time) -> bit-packed spikes via ballot.
// One warp handles (b, word w): lane l owns h = w*32 + l. 25 words out.
// ---------------------------------------------------------------------------
__global__ void __launch_bounds__(256) k1_spikes() {
    int gw = blockIdx.x * 8 + (threadIdx.x >> 5);        // global warp < 65536*32
    int lane = threadIdx.x & 31;
    size_t b = (size_t)(gw >> 5);
    int w = gw & 31;
    float c = g_cur1[b * H1 + w * 32 + lane];
    float m = 0.0f, s;
    #pragma unroll
    for (int t = 0; t < TSTEPS; t++) {
        lif_step(m, c, s);
        uint32_t bits = __ballot_sync(0xffffffffu, s > 0.5f);
        if (lane == 0)
            g_spk1b[((size_t)t * BATCH + b) * 32 + w] = bits;
    }
}

// ---------------------------------------------------------------------------
// Kernel 2 (x25, one per timestep): cur2 = spk1_t @ (W2hi+W2lo) + b2, fused
// layer-2 LIF epilogue updating g_mem2 and emitting spk2 bits.
// CTA tile: 128(M=batch) x 256(N), K=1024, Kc=64, double buffered.
// A: bit words -> bf16 expand in registers -> STS. B: cp.async (hi+lo limbs).
// 8 warps 2x4; warp tile 64x64 m16n8k16. SMEM rows 144B (conflict-free ldmatrix).
// ---------------------------------------------------------------------------
#define KC          64
#define A_BYTES     (128 * 144)
#define B_BYTES     (256 * 144)
#define BUF_BYTES   (A_BYTES + 2 * B_BYTES)   // 92160
#define GSM_TOTAL   (2 * BUF_BYTES)           // 184320

__device__ __forceinline__ void stage_chunk(char* smem, uint32_t sb, int p,
                                            int t, size_t m0, int n0,
                                            int k0, int tid) {
    char* bufc = smem + (size_t)p * BUF_BYTES;
    uint32_t base = sb + (uint32_t)p * BUF_BYTES;
    // A: expand bits -> bf16. thread: row = tid>>1, 32-k half = tid&1.
    {
        int row = tid >> 1, half = tid & 1;
        uint32_t u = g_spk1b[((size_t)t * BATCH + m0 + row) * 32 + (k0 >> 5) + half];
        char* dst = bufc + row * 144 + half * 64;
        #pragma unroll
        for (int q4 = 0; q4 < 4; q4++) {
            uint4 v;
            uint32_t s = u >> (q4 * 8);
            v.x = ((s      ) & 1) * 0x3F80u | ((s >> 1) & 1) * 0x3F800000u;
            v.y = ((s >> 2) & 1) * 0x3F80u | ((s >> 3) & 1) * 0x3F800000u;
            v.z = ((s >> 4) & 1) * 0x3F80u | ((s >> 5) & 1) * 0x3F800000u;
            v.w = ((s >> 6) & 1) * 0x3F80u | ((s >> 7) & 1) * 0x3F800000u;
            *(uint4*)(dst + q4 * 16) = v;
        }
    }
    // B hi & lo: 256 rows x 64 bf16 each = 2048 x 16B each
    #pragma unroll
    for (int limb = 0; limb < 2; limb++) {
        const __nv_bfloat16* W = limb ? g_w2lo : g_w2hi;
        uint32_t bb = base + A_BYTES + (uint32_t)limb * B_BYTES;
        #pragma unroll
        for (int it = 0; it < 8; it++) {
            int idx = tid + it * 256;
            int row = idx >> 3, j = idx & 7;
            CP_ASYNC16(bb + row * 144 + j * 16,
                       W + (size_t)(n0 + row) * H1 + k0 + j * 8);
        }
    }
}

__global__ void __launch_bounds__(256, 1) k2_gemm2(int t, const float* __restrict__ b2) {
    extern __shared__ char smem[];
    uint32_t sb = smem_to_u32(smem);
    int tid  = threadIdx.x;
    int lane = tid & 31;
    int wid  = tid >> 5;
    int wm   = wid >> 2;          // 0..1  (M)
    int wn   = wid & 3;           // 0..3  (N)

    size_t m0 = (size_t)(blockIdx.x >> 1) * 128;
    int    n0 = (blockIdx.x & 1) * 256;
    int    ng = n0 + wn * 64;

    float acc[4][8][4];
    #pragma unroll
    for (int i = 0; i < 4; i++)
        #pragma unroll
        for (int j = 0; j < 8; j++)
            #pragma unroll
            for (int q = 0; q < 4; q++) acc[i][j][q] = 0.0f;

    stage_chunk(smem, sb, 0, t, m0, n0, 0, tid);
    CP_COMMIT();

    #pragma unroll 1
    for (int ic = 0; ic < 16; ic++) {
        int p = ic & 1;
        if (ic < 15) {
            stage_chunk(smem, sb, p ^ 1, t, m0, n0, (ic + 1) * KC, tid);
            CP_COMMIT();
            CP_WAIT1();
        } else {
            CP_WAIT0();
        }
        __syncthreads();

        uint32_t bufb   = sb + (uint32_t)p * BUF_BYTES;
        uint32_t aBase  = bufb + (uint32_t)(wm * 64 + (lane & 15)) * 144 + (uint32_t)((lane >> 4) * 16);
        uint32_t bRow   = (uint32_t)(wn * 64 + (lane & 15)) * 144 + (uint32_t)((lane >> 4) * 16);
        uint32_t bBaseH = bufb + A_BYTES + bRow;
        uint32_t bBaseL = bufb + A_BYTES + B_BYTES + bRow;

        #pragma unroll
        for (int ks = 0; ks < 4; ks++) {
            uint32_t a[4][4];
            #pragma unroll
            for (int mt = 0; mt < 4; mt++)
                LDMX4(a[mt], aBase + mt * 2304 + ks * 32);
            #pragma unroll
            for (int limb = 0; limb < 2; limb++) {
                uint32_t bb = limb ? bBaseL : bBaseH;
                #pragma unroll
                for (int jb = 0; jb < 4; jb++) {
                    uint32_t b[4];
                    LDMX4(b, bb + jb * 2304 + ks * 32);
                    #pragma unroll
                    for (int mt = 0; mt < 4; mt++) {
                        MMA_BF16(acc[mt][jb * 2 + 0], a[mt], b[0], b[2]);
                        MMA_BF16(acc[mt][jb * 2 + 1], a[mt], b[1], b[3]);
                    }
                }
            }
        }
        __syncthreads();
    }

    // --- Fused epilogue: cur2 = acc + b2; LIF2 on g_mem2; emit spk2 bits. ---
    // D frag (m16n8): c0/c1 at (row = lane>>2, col = (lane&3)*2), c2/c3 at row+8.
    {
        float b2r[16];
        #pragma unroll
        for (int nf = 0; nf < 8; nf++) {
            int c = ng + nf * 8 + (lane & 3) * 2;
            b2r[nf * 2 + 0] = b2[c];
            b2r[nf * 2 + 1] = b2[c + 1];
        }
        bool first = (t == 0);
        size_t mg = m0 + (size_t)wm * 64;
        #pragma unroll
        for (int mt = 0; mt < 4; mt++) {
            #pragma unroll
            for (int half = 0; half < 2; half++) {
                size_t row = mg + mt * 16 + (lane >> 2) + half * 8;
                float* m2p = g_mem2 + row * H2;
                uint32_t wbits[2] = {0u, 0u};
                #pragma unroll
                for (int nf = 0; nf < 8; nf++) {
                    int c = ng + nf * 8 + (lane & 3) * 2;
                    float a0 = __fadd_rn(acc[mt][nf][half * 2 + 0], b2r[nf * 2 + 0]);
                    float a1 = __fadd_rn(acc[mt][nf][half * 2 + 1], b2r[nf * 2 + 1]);
                    float mA, mB;
                    if (first) { mA = 0.0f; mB = 0.0f; }
                    else { float2 mv = *(float2*)(m2p + c); mA = mv.x; mB = mv.y; }
                    float sA, sB;
                    lif_step(mA, a0, sA);
                    lif_step(mB, a1, sB);
                    *(float2*)(m2p + c) = make_float2(mA, mB);
                    // bit position within the 32-bit word covering cols
                    // [ng + (nf>>2)*32, +32): nf selects byte-pair, lane quad
                    // selects 2-bit slot.
                    int bp = (nf & 3) * 8 + (lane & 3) * 2;
                    uint32_t bits = ((sA > 0.5f) ? 1u : 0u) << bp
                                  | ((sB > 0.5f) ? 1u : 0u) << (bp + 1);
                    wbits[nf >> 2] |= bits;
                }
                // OR across the 4 lanes of the quad (lanes sharing this row)
                wbits[0] |= __shfl_xor_sync(0xffffffffu, wbits[0], 1);
                wbits[0] |= __shfl_xor_sync(0xffffffffu, wbits[0], 2);
                wbits[1] |= __shfl_xor_sync(0xffffffffu, wbits[1], 1);
                wbits[1] |= __shfl_xor_sync(0xffffffffu, wbits[1], 2);
                if ((lane & 3) == 0) {
                    size_t widx = ((size_t)t * BATCH + row) * 16 + (ng >> 5);
                    g_spk2b[widx]     = wbits[0];
                    g_spk2b[widx + 1] = wbits[1];
                }
            }
        }
    }
}

// ---------------------------------------------------------------------------
// Kernel 3: layer-3 recurrence + output from spk2 bits. One warp per batch row.
// lane owns n = lane*16 .. +15 (half of word lane>>1).
// ---------------------------------------------------------------------------
__global__ void __launch_bounds__(256) k3_output(const float* __restrict__ W3,
                                                 const float* __restrict__ b3,
                                                 float* __restrict__ out) {
    int warp = (blockIdx.x * 256 + threadIdx.x) >> 5;
    int lane = threadIdx.x & 31;
    if (warp >= BATCH) return;
    size_t b = (size_t)warp;

    float w3r[16];
    #pragma unroll
    for (int j = 0; j < 16; j++) w3r[j] = W3[lane * 16 + j];
    float bb3 = b3[0];
    float mem3 = 0.0f, accm = 0.0f;

    for (int t = 0; t < TSTEPS; t++) {
        uint32_t word = g_spk2b[((size_t)t * BATCH + b) * 16 + (lane >> 1)];
        uint32_t half = (word >> ((lane & 1) * 16)) & 0xFFFFu;
        float cs = 0.0f;
        #pragma unroll
        for (int j = 0; j < 16; j++)
            if ((half >> j) & 1) cs += w3r[j];
        #pragma unroll
        for (int o = 16; o > 0; o >>= 1)
            cs += __shfl_xor_sync(0xffffffffu, cs, o);
        float cur3 = __fadd_rn(cs, bb3);
        float r3 = (mem3 > 1.0f) ? 1.0f : 0.0f;
        mem3 = __fsub_rn(__fadd_rn(__fmul_rn(BETA, mem3), cur3), r3);
        accm += mem3;
    }
    if (lane == 0) {
        float m = accm / 25.0f;
        out[warp] = 1.0f / (1.0f + expf(-m));
    }
}

// ---------------------------------------------------------------------------
// Launch
// ---------------------------------------------------------------------------
extern "C" void kernel_launch(void* const* d_in, const int* in_sizes, int n_in,
                              void* d_out, int out_size) {
    const float* x  = (const float*)d_in[0];
    const float* W1 = (const float*)d_in[1];
    const float* b1 = (const float*)d_in[2];
    const float* W2 = (const float*)d_in[3];
    const float* b2 = (const float*)d_in[4];
    const float* W3 = (const float*)d_in[5];
    const float* b3 = (const float*)d_in[6];
    float* out = (float*)d_out;

    cudaFuncSetAttribute(k2_gemm2, cudaFuncAttributeMaxDynamicSharedMemorySize, GSM_TOTAL);

    k_prep_w2<<<(H1 * H2) / 256, 256>>>(W2);
    k0_gemm1<<<(BATCH / 64) * (H1 / 64), 256>>>(x, W1, b1);
    k1_spikes<<<(BATCH * 32) / 8, 256>>>();
    for (int t = 0; t < TSTEPS; t++)
        k2_gemm2<<<1024, 256, GSM_TOTAL>>>(t, b2);
    k3_output<<<(BATCH * 32) / 256, 256>>>(W3, b3, out);
}

// round 16
// speedup vs baseline: 1.1033x; 1.1033x over previous
#include <cuda_runtime.h>
#include <cuda_bf16.h>
#include <cstdint>
#include <math.h>

// ---------------------------------------------------------------------------
// Problem constants
// ---------------------------------------------------------------------------
#define BATCH   65536
#define TSTEPS  25
#define H1      1024
#define H2      512
#define DIN     64
#define BETA    0.95f

// ---------------------------------------------------------------------------
// Device scratch — total ~720 MB (must stay < ~2 GB: aarch64 .bss reloc range)
// ---------------------------------------------------------------------------
__device__ float          g_cur1[(size_t)BATCH * H1];                    // 268 MB
__device__ uint32_t       g_spk1b[(size_t)TSTEPS * BATCH * (H1 / 32)];   // 210 MB (bit k)
__device__ uint32_t       g_spk2b[(size_t)TSTEPS * BATCH * (H2 / 32)];   // 105 MB (bit n)
__device__ float          g_mem2[(size_t)BATCH * H2];                    // 134 MB
__device__ __nv_bfloat16  g_w2hi[(size_t)H2 * H1];                       // [n][k]
__device__ __nv_bfloat16  g_w2lo[(size_t)H2 * H1];                       // [n][k]

// ---------------------------------------------------------------------------
// PTX helpers — sm_80+ only (toolchain lowers via compute_103 base target;
// tcgen05 / 'a'-features unavailable)
// ---------------------------------------------------------------------------
__device__ __forceinline__ uint32_t smem_to_u32(const void* p) {
    uint32_t a;
    asm("{ .reg .u64 t; cvta.to.shared.u64 t, %1; cvt.u32.u64 %0, t; }" : "=r"(a) : "l"(p));
    return a;
}

#define CP_ASYNC16(dst_u32, src_ptr) do {                                        \
    unsigned long long _g = __cvta_generic_to_global((const void*)(src_ptr));    \
    asm volatile("cp.async.cg.shared.global [%0], [%1], 16;"                     \
                 :: "r"(dst_u32), "l"(_g) : "memory");                           \
} while (0)
#define CP_COMMIT()  asm volatile("cp.async.commit_group;" ::: "memory")
#define CP_WAIT1()   asm volatile("cp.async.wait_group 1;" ::: "memory")
#define CP_WAIT0()   asm volatile("cp.async.wait_group 0;" ::: "memory")

#define LDMX4(r, addr)                                                           \
    asm volatile("ldmatrix.sync.aligned.m8n8.x4.shared.b16 {%0,%1,%2,%3}, [%4];" \
        : "=r"((r)[0]), "=r"((r)[1]), "=r"((r)[2]), "=r"((r)[3]) : "r"(addr))

#define MMA_BF16(d, a, b0_, b1_)                                                 \
    asm volatile("mma.sync.aligned.m16n8k16.row.col.f32.bf16.bf16.f32 "          \
        "{%0,%1,%2,%3}, {%4,%5,%6,%7}, {%8,%9}, {%0,%1,%2,%3};"                  \
        : "+f"((d)[0]), "+f"((d)[1]), "+f"((d)[2]), "+f"((d)[3])                 \
        : "r"((a)[0]), "r"((a)[1]), "r"((a)[2]), "r"((a)[3]), "r"(b0_), "r"(b1_))

// Exact (non-fma-contracted) LIF step matching jnp:  m = B*m + c - r
__device__ __forceinline__ void lif_step(float& m, float c, float& spk) {
    float r = (m > 1.0f) ? 1.0f : 0.0f;
    m = __fsub_rn(__fadd_rn(__fmul_rn(BETA, m), c), r);
    spk = (m > 1.0f) ? 1.0f : 0.0f;
}

// ---------------------------------------------------------------------------
// Kernel P: two-limb bf16 split of W2, transposed to [n][k] (B operand).
// ---------------------------------------------------------------------------
__global__ void __launch_bounds__(256) k_prep_w2(const float* __restrict__ W2) {
    int idx = blockIdx.x * 256 + threadIdx.x;            // < 1024*512
    int k = idx >> 9;
    int n = idx & 511;
    float w = W2[(size_t)k * H2 + n];
    __nv_bfloat16 hi = __float2bfloat16(w);
    float r = w - __bfloat162float(hi);                  // exact residual
    g_w2hi[(size_t)n * H1 + k] = hi;
    g_w2lo[(size_t)n * H1 + k] = __float2bfloat16(r);
}

// ---------------------------------------------------------------------------
// Kernel 0: cur1 = x@W1 + b1 (fp32 SIMT GEMM, K=64). Tile 64x64, thread 4x4.
// ---------------------------------------------------------------------------
__global__ void __launch_bounds__(256) k0_gemm1(const float* __restrict__ x,
                                                const float* __restrict__ W1,
                                                const float* __restrict__ b1) {
    __shared__ float xs[64][65];
    __shared__ float ws[64][64];
    int hb = blockIdx.x & 15, bb = blockIdx.x >> 4;
    int b0 = bb * 64, h0 = hb * 64;
    int tid = threadIdx.x;

    for (int i = tid; i < 4096; i += 256) {
        int r = i >> 6, c = i & 63;
        xs[r][c] = x[(size_t)(b0 + r) * DIN + c];
        ws[r][c] = W1[(size_t)r * H1 + h0 + c];
    }
    __syncthreads();

    int tx = tid & 15, ty = tid >> 4;
    float acc[4][4] = {};
    #pragma unroll 8
    for (int k = 0; k < 64; k++) {
        float a0 = xs[ty * 4 + 0][k], a1 = xs[ty * 4 + 1][k];
        float a2 = xs[ty * 4 + 2][k], a3 = xs[ty * 4 + 3][k];
        float w0 = ws[k][tx * 4 + 0], w1 = ws[k][tx * 4 + 1];
        float w2 = ws[k][tx * 4 + 2], w3 = ws[k][tx * 4 + 3];
        acc[0][0] += a0 * w0; acc[0][1] += a0 * w1; acc[0][2] += a0 * w2; acc[0][3] += a0 * w3;
        acc[1][0] += a1 * w0; acc[1][1] += a1 * w1; acc[1][2] += a1 * w2; acc[1][3] += a1 * w3;
        acc[2][0] += a2 * w0; acc[2][1] += a2 * w1; acc[2][2] += a2 * w2; acc[2][3] += a2 * w3;
        acc[3][0] += a3 * w0; acc[3][1] += a3 * w1; acc[3][2] += a3 * w2; acc[3][3] += a3 * w3;
    }
    float c0 = b1[h0 + tx * 4 + 0], c1 = b1[h0 + tx * 4 + 1];
    float c2 = b1[h0 + tx * 4 + 2], c3 = b1[h0 + tx * 4 + 3];
    #pragma unroll
    for (int i = 0; i < 4; i++) {
        float4 v;
        v.x = acc[i][0] + c0; v.y = acc[i][1] + c1;
        v.z = acc[i][2] + c2; v.w = acc[i][3] + c3;
        *(float4*)(g_cur1 + (size_t)(b0 + ty * 4 + i) * H1 + h0 + tx * 4) = v;
    }
}

// ---------------------------------------------------------------------------
// Kernel 1: layer-1 LIF (cur1 static in time) -> bit-packed spikes via ballot.
// ---------------------------------------------------------------------------
__global__ void __launch_bounds__(256) k1_spikes() {
    int gw = blockIdx.x * 8 + (threadIdx.x >> 5);        // global warp < 65536*32
    int lane = threadIdx.x & 31;
    size_t b = (size_t)(gw >> 5);
    int w = gw & 31;
    float c = g_cur1[b * H1 + w * 32 + lane];
    float m = 0.0f, s;
    #pragma unroll
    for (int t = 0; t < TSTEPS; t++) {
        lif_step(m, c, s);
        uint32_t bits = __ballot_sync(0xffffffffu, s > 0.5f);
        if (lane == 0)
            g_spk1b[((size_t)t * BATCH + b) * 32 + w] = bits;
    }
}

// ---------------------------------------------------------------------------
// Kernel 2 (single launch, t-loop inside): cur2 = spk1_t @ (W2hi+W2lo) + b2,
// fused layer-2 LIF epilogue updating g_mem2 and emitting spk2 bits.
// CTA tile: 128(M) x 128(N), Kc=64, double buffered; 8 warps 2x4, warp 64x32.
// smem/CTA = 110,592 B + regs<=128  =>  2 CTAs/SM to hide sync/staging bubbles.
// Per-element accumulation order (chunk asc, ks asc, limb hi->lo) identical to
// the R15 kernel -> bit-identical output.
// ---------------------------------------------------------------------------
#define KC          64
#define A_BYTES     (128 * 144)               // 18432
#define B_BYTES     (128 * 144)               // 18432 per limb
#define BUF_BYTES   (A_BYTES + 2 * B_BYTES)   // 55296
#define GSM_TOTAL   (2 * BUF_BYTES)           // 110592

__device__ __forceinline__ void stage_chunk(char* smem, uint32_t sb, int p,
                                            int t, size_t m0, int n0,
                                            int k0, int tid) {
    char* bufc = smem + (size_t)p * BUF_BYTES;
    uint32_t base = sb + (uint32_t)p * BUF_BYTES;
    // A: expand spike bits -> bf16. thread: row = tid>>1, 32-k half = tid&1.
    {
        int row = tid >> 1, half = tid & 1;
        uint32_t u = g_spk1b[((size_t)t * BATCH + m0 + row) * 32 + (k0 >> 5) + half];
        char* dst = bufc + row * 144 + half * 64;
        #pragma unroll
        for (int q4 = 0; q4 < 4; q4++) {
            uint4 v;
            uint32_t s = u >> (q4 * 8);
            v.x = ((s      ) & 1) * 0x3F80u | ((s >> 1) & 1) * 0x3F800000u;
            v.y = ((s >> 2) & 1) * 0x3F80u | ((s >> 3) & 1) * 0x3F800000u;
            v.z = ((s >> 4) & 1) * 0x3F80u | ((s >> 5) & 1) * 0x3F800000u;
            v.w = ((s >> 6) & 1) * 0x3F80u | ((s >> 7) & 1) * 0x3F800000u;
            *(uint4*)(dst + q4 * 16) = v;
        }
    }
    // B hi & lo: 128 rows x 64 bf16 each = 1024 x 16B chunks per limb
    #pragma unroll
    for (int limb = 0; limb < 2; limb++) {
        const __nv_bfloat16* W = limb ? g_w2lo : g_w2hi;
        uint32_t bb = base + A_BYTES + (uint32_t)limb * B_BYTES;
        #pragma unroll
        for (int it = 0; it < 4; it++) {
            int idx = tid + it * 256;
            int row = idx >> 3, j = idx & 7;
            CP_ASYNC16(bb + row * 144 + j * 16,
                       W + (size_t)(n0 + row) * H1 + k0 + j * 8);
        }
    }
}

__global__ void __launch_bounds__(256, 2) k2_gemm2(const float* __restrict__ b2) {
    extern __shared__ char smem[];
    uint32_t sb = smem_to_u32(smem);
    int tid  = threadIdx.x;
    int lane = tid & 31;
    int wid  = tid >> 5;
    int wm   = wid >> 2;          // 0..1  (M)
    int wn   = wid & 3;           // 0..3  (N)

    size_t m0 = (size_t)(blockIdx.x >> 2) * 128;
    int    n0 = (blockIdx.x & 3) * 128;
    int    ng = n0 + wn * 32;

    // b2 fragment (8 cols owned by this thread), loaded once
    float b2r[8];
    #pragma unroll
    for (int nf = 0; nf < 4; nf++) {
        int c = ng + nf * 8 + (lane & 3) * 2;
        b2r[nf * 2 + 0] = b2[c];
        b2r[nf * 2 + 1] = b2[c + 1];
    }

    float acc[4][4][4];
    #pragma unroll
    for (int i = 0; i < 4; i++)
        #pragma unroll
        for (int j = 0; j < 4; j++)
            #pragma unroll
            for (int q = 0; q < 4; q++) acc[i][j][q] = 0.0f;

    stage_chunk(smem, sb, 0, 0, m0, n0, 0, tid);
    CP_COMMIT();

    // 400 fused chunks: c -> (t = c>>4, k0 = (c&15)*KC)
    #pragma unroll 1
    for (int c = 0; c < 400; c++) {
        int p = c & 1;
        if (c < 399) {
            int nc = c + 1;
            stage_chunk(smem, sb, p ^ 1, nc >> 4, m0, n0, (nc & 15) * KC, tid);
            CP_COMMIT();
            CP_WAIT1();
        } else {
            CP_WAIT0();
        }
        __syncthreads();

        uint32_t bufb  = sb + (uint32_t)p * BUF_BYTES;
        uint32_t aBase = bufb + (uint32_t)(wm * 64 + (lane & 15)) * 144 + (uint32_t)((lane >> 4) * 16);
        uint32_t bRow  = (uint32_t)(wn * 32 + (lane & 15)) * 144 + (uint32_t)((lane >> 4) * 16);
        uint32_t bH    = bufb + A_BYTES + bRow;
        uint32_t bL    = bH + B_BYTES;

        #pragma unroll
        for (int ks = 0; ks < 4; ks++) {
            uint32_t a[4][4];
            #pragma unroll
            for (int mt = 0; mt < 4; mt++)
                LDMX4(a[mt], aBase + mt * 2304 + ks * 32);
            #pragma unroll
            for (int limb = 0; limb < 2; limb++) {
                uint32_t bb = limb ? bL : bH;
                #pragma unroll
                for (int jb = 0; jb < 2; jb++) {
                    uint32_t b[4];
                    LDMX4(b, bb + jb * 2304 + ks * 32);
                    #pragma unroll
                    for (int mt = 0; mt < 4; mt++) {
                        MMA_BF16(acc[mt][jb * 2 + 0], a[mt], b[0], b[2]);
                        MMA_BF16(acc[mt][jb * 2 + 1], a[mt], b[1], b[3]);
                    }
                }
            }
        }
        __syncthreads();

        // --- End of timestep: fused epilogue (LIF2 on g_mem2, spk2 bits) ---
        if ((c & 15) == 15) {
            int t = c >> 4;
            bool first = (t == 0);
            size_t mgw = m0 + (size_t)wm * 64;
            #pragma unroll
            for (int mt = 0; mt < 4; mt++) {
                #pragma unroll
                for (int half = 0; half < 2; half++) {
                    size_t row = mgw + mt * 16 + (lane >> 2) + half * 8;
                    float* m2p = g_mem2 + row * H2;
                    uint32_t wbits = 0u;
                    #pragma unroll
                    for (int nf = 0; nf < 4; nf++) {
                        int cc = ng + nf * 8 + (lane & 3) * 2;
                        float a0 = __fadd_rn(acc[mt][nf][half * 2 + 0], b2r[nf * 2 + 0]);
                        float a1 = __fadd_rn(acc[mt][nf][half * 2 + 1], b2r[nf * 2 + 1]);
                        float mA, mB;
                        if (first) { mA = 0.0f; mB = 0.0f; }
                        else { float2 mv = *(float2*)(m2p + cc); mA = mv.x; mB = mv.y; }
                        float sA, sB;
                        lif_step(mA, a0, sA);
                        lif_step(mB, a1, sB);
                        *(float2*)(m2p + cc) = make_float2(mA, mB);
                        int bp = nf * 8 + (lane & 3) * 2;
                        wbits |= ((sA > 0.5f) ? 1u : 0u) << bp
                               | ((sB > 0.5f) ? 1u : 0u) << (bp + 1);
                    }
                    wbits |= __shfl_xor_sync(0xffffffffu, wbits, 1);
                    wbits |= __shfl_xor_sync(0xffffffffu, wbits, 2);
                    if ((lane & 3) == 0)
                        g_spk2b[((size_t)t * BATCH + row) * 16 + (ng >> 5)] = wbits;
                }
            }
            // reset accumulators for next timestep
            #pragma unroll
            for (int i = 0; i < 4; i++)
                #pragma unroll
                for (int j = 0; j < 4; j++)
                    #pragma unroll
                    for (int q = 0; q < 4; q++) acc[i][j][q] = 0.0f;
        }
    }
}

// ---------------------------------------------------------------------------
// Kernel 3: layer-3 recurrence + output from spk2 bits. One warp per batch row.
// ---------------------------------------------------------------------------
__global__ void __launch_bounds__(256) k3_output(const float* __restrict__ W3,
                                                 const float* __restrict__ b3,
                                                 float* __restrict__ out) {
    int warp = (blockIdx.x * 256 + threadIdx.x) >> 5;
    int lane = threadIdx.x & 31;
    if (warp >= BATCH) return;
    size_t b = (size_t)warp;

    float w3r[16];
    #pragma unroll
    for (int j = 0; j < 16; j++) w3r[j] = W3[lane * 16 + j];
    float bb3 = b3[0];
    float mem3 = 0.0f, accm = 0.0f;

    for (int t = 0; t < TSTEPS; t++) {
        uint32_t word = g_spk2b[((size_t)t * BATCH + b) * 16 + (lane >> 1)];
        uint32_t half = (word >> ((lane & 1) * 16)) & 0xFFFFu;
        float cs = 0.0f;
        #pragma unroll
        for (int j = 0; j < 16; j++)
            if ((half >> j) & 1) cs += w3r[j];
        #pragma unroll
        for (int o = 16; o > 0; o >>= 1)
            cs += __shfl_xor_sync(0xffffffffu, cs, o);
        float cur3 = __fadd_rn(cs, bb3);
        float r3 = (mem3 > 1.0f) ? 1.0f : 0.0f;
        mem3 = __fsub_rn(__fadd_rn(__fmul_rn(BETA, mem3), cur3), r3);
        accm += mem3;
    }
    if (lane == 0) {
        float m = accm / 25.0f;
        out[warp] = 1.0f / (1.0f + expf(-m));
    }
}

// ---------------------------------------------------------------------------
// Launch
// ---------------------------------------------------------------------------
extern "C" void kernel_launch(void* const* d_in, const int* in_sizes, int n_in,
                              void* d_out, int out_size) {
    const float* x  = (const float*)d_in[0];
    const float* W1 = (const float*)d_in[1];
    const float* b1 = (const float*)d_in[2];
    const float* W2 = (const float*)d_in[3];
    const float* b2 = (const float*)d_in[4];
    const float* W3 = (const float*)d_in[5];
    const float* b3 = (const float*)d_in[6];
    float* out = (float*)d_out;

    cudaFuncSetAttribute(k2_gemm2, cudaFuncAttributeMaxDynamicSharedMemorySize, GSM_TOTAL);

    k_prep_w2<<<(H1 * H2) / 256, 256>>>(W2);
    k0_gemm1<<<(BATCH / 64) * (H1 / 64), 256>>>(x, W1, b1);
    k1_spikes<<<(BATCH * 32) / 8, 256>>>();
    k2_gemm2<<<(BATCH / 128) * (H2 / 128), 256, GSM_TOTAL>>>(b2);
    k3_output<<<(BATCH * 32) / 256, 256>>>(W3, b3, out);
}

// round 17
// speedup vs baseline: 1.1210x; 1.0160x over previous
#include <cuda_runtime.h>
#include <cuda_bf16.h>
#include <cstdint>
#include <math.h>

// ---------------------------------------------------------------------------
// Problem constants
// ---------------------------------------------------------------------------
#define BATCH   65536
#define TSTEPS  25
#define H1      1024
#define H2      512
#define DIN     64
#define BETA    0.95f

// ---------------------------------------------------------------------------
// Device scratch — total ~720 MB (must stay < ~2 GB: aarch64 .bss reloc range)
// ---------------------------------------------------------------------------
__device__ float          g_cur1[(size_t)BATCH * H1];                    // 268 MB
__device__ uint32_t       g_spk1b[(size_t)TSTEPS * BATCH * (H1 / 32)];   // 210 MB (bit k)
__device__ uint32_t       g_spk2b[(size_t)TSTEPS * BATCH * (H2 / 32)];   // 105 MB (bit n)
__device__ float          g_mem2[(size_t)BATCH * H2];                    // 134 MB
__device__ __nv_bfloat16  g_w2hi[(size_t)H2 * H1];                       // [n][k]
__device__ __nv_bfloat16  g_w2lo[(size_t)H2 * H1];                       // [n][k]

// ---------------------------------------------------------------------------
// PTX helpers — sm_80+ only (toolchain lowers via compute_103 base target;
// tcgen05 / 'a'-features unavailable)
// ---------------------------------------------------------------------------
__device__ __forceinline__ uint32_t smem_to_u32(const void* p) {
    uint32_t a;
    asm("{ .reg .u64 t; cvta.to.shared.u64 t, %1; cvt.u32.u64 %0, t; }" : "=r"(a) : "l"(p));
    return a;
}

#define CP_ASYNC16(dst_u32, src_ptr) do {                                        \
    unsigned long long _g = __cvta_generic_to_global((const void*)(src_ptr));    \
    asm volatile("cp.async.cg.shared.global [%0], [%1], 16;"                     \
                 :: "r"(dst_u32), "l"(_g) : "memory");                           \
} while (0)
#define CP_ASYNC4(dst_u32, src_ptr) do {                                         \
    unsigned long long _g = __cvta_generic_to_global((const void*)(src_ptr));    \
    asm volatile("cp.async.ca.shared.global [%0], [%1], 4;"                      \
                 :: "r"(dst_u32), "l"(_g) : "memory");                           \
} while (0)
#define CP_COMMIT()  asm volatile("cp.async.commit_group;" ::: "memory")
#define CP_WAIT0()   asm volatile("cp.async.wait_group 0;" ::: "memory")

#define LDMX4(r, addr)                                                           \
    asm volatile("ldmatrix.sync.aligned.m8n8.x4.shared.b16 {%0,%1,%2,%3}, [%4];" \
        : "=r"((r)[0]), "=r"((r)[1]), "=r"((r)[2]), "=r"((r)[3]) : "r"(addr))

#define MMA_BF16(d, a, b0_, b1_)                                                 \
    asm volatile("mma.sync.aligned.m16n8k16.row.col.f32.bf16.bf16.f32 "          \
        "{%0,%1,%2,%3}, {%4,%5,%6,%7}, {%8,%9}, {%0,%1,%2,%3};"                  \
        : "+f"((d)[0]), "+f"((d)[1]), "+f"((d)[2]), "+f"((d)[3])                 \
        : "r"((a)[0]), "r"((a)[1]), "r"((a)[2]), "r"((a)[3]), "r"(b0_), "r"(b1_))

// Exact (non-fma-contracted) LIF step matching jnp:  m = B*m + c - r
__device__ __forceinline__ void lif_step(float& m, float c, float& spk) {
    float r = (m > 1.0f) ? 1.0f : 0.0f;
    m = __fsub_rn(__fadd_rn(__fmul_rn(BETA, m), c), r);
    spk = (m > 1.0f) ? 1.0f : 0.0f;
}

// ---------------------------------------------------------------------------
// Kernel P: two-limb bf16 split of W2, transposed to [n][k] (B operand).
// ---------------------------------------------------------------------------
__global__ void __launch_bounds__(256) k_prep_w2(const float* __restrict__ W2) {
    int idx = blockIdx.x * 256 + threadIdx.x;            // < 1024*512
    int k = idx >> 9;
    int n = idx & 511;
    float w = W2[(size_t)k * H2 + n];
    __nv_bfloat16 hi = __float2bfloat16(w);
    float r = w - __bfloat162float(hi);                  // exact residual
    g_w2hi[(size_t)n * H1 + k] = hi;
    g_w2lo[(size_t)n * H1 + k] = __float2bfloat16(r);
}

// ---------------------------------------------------------------------------
// Kernel 0: cur1 = x@W1 + b1 (fp32 SIMT GEMM, K=64). Tile 64x64, thread 4x4.
// ---------------------------------------------------------------------------
__global__ void __launch_bounds__(256) k0_gemm1(const float* __restrict__ x,
                                                const float* __restrict__ W1,
                                                const float* __restrict__ b1) {
    __shared__ float xs[64][65];
    __shared__ float ws[64][64];
    int hb = blockIdx.x & 15, bb = blockIdx.x >> 4;
    int b0 = bb * 64, h0 = hb * 64;
    int tid = threadIdx.x;

    for (int i = tid; i < 4096; i += 256) {
        int r = i >> 6, c = i & 63;
        xs[r][c] = x[(size_t)(b0 + r) * DIN + c];
        ws[r][c] = W1[(size_t)r * H1 + h0 + c];
    }
    __syncthreads();

    int tx = tid & 15, ty = tid >> 4;
    float acc[4][4] = {};
    #pragma unroll 8
    for (int k = 0; k < 64; k++) {
        float a0 = xs[ty * 4 + 0][k], a1 = xs[ty * 4 + 1][k];
        float a2 = xs[ty * 4 + 2][k], a3 = xs[ty * 4 + 3][k];
        float w0 = ws[k][tx * 4 + 0], w1 = ws[k][tx * 4 + 1];
        float w2 = ws[k][tx * 4 + 2], w3 = ws[k][tx * 4 + 3];
        acc[0][0] += a0 * w0; acc[0][1] += a0 * w1; acc[0][2] += a0 * w2; acc[0][3] += a0 * w3;
        acc[1][0] += a1 * w0; acc[1][1] += a1 * w1; acc[1][2] += a1 * w2; acc[1][3] += a1 * w3;
        acc[2][0] += a2 * w0; acc[2][1] += a2 * w1; acc[2][2] += a2 * w2; acc[2][3] += a2 * w3;
        acc[3][0] += a3 * w0; acc[3][1] += a3 * w1; acc[3][2] += a3 * w2; acc[3][3] += a3 * w3;
    }
    float c0 = b1[h0 + tx * 4 + 0], c1 = b1[h0 + tx * 4 + 1];
    float c2 = b1[h0 + tx * 4 + 2], c3 = b1[h0 + tx * 4 + 3];
    #pragma unroll
    for (int i = 0; i < 4; i++) {
        float4 v;
        v.x = acc[i][0] + c0; v.y = acc[i][1] + c1;
        v.z = acc[i][2] + c2; v.w = acc[i][3] + c3;
        *(float4*)(g_cur1 + (size_t)(b0 + ty * 4 + i) * H1 + h0 + tx * 4) = v;
    }
}

// ---------------------------------------------------------------------------
// Kernel 1: layer-1 LIF (cur1 static in time) -> bit-packed spikes via ballot.
// ---------------------------------------------------------------------------
__global__ void __launch_bounds__(256) k1_spikes() {
    int gw = blockIdx.x * 8 + (threadIdx.x >> 5);        // global warp < 65536*32
    int lane = threadIdx.x & 31;
    size_t b = (size_t)(gw >> 5);
    int w = gw & 31;
    float c = g_cur1[b * H1 + w * 32 + lane];
    float m = 0.0f, s;
    #pragma unroll
    for (int t = 0; t < TSTEPS; t++) {
        lif_step(m, c, s);
        uint32_t bits = __ballot_sync(0xffffffffu, s > 0.5f);
        if (lane == 0)
            g_spk1b[((size_t)t * BATCH + b) * 32 + w] = bits;
    }
}

// ---------------------------------------------------------------------------
// Kernel 2 (single launch, t-loop inside): cur2 = spk1_t @ (W2hi+W2lo) + b2,
// fused layer-2 LIF epilogue updating g_mem2 and emitting spk2 bits.
// CTA tile: 128(M) x 128(N), Kc=64, double buffered; 8 warps 2x4, warp 64x32.
// ALL staging (A spike bits AND B limbs) via cp.async, one chunk ahead:
// nothing on the per-chunk critical path waits on DRAM. A-bits land in a
// 1KB smem region, expanded bits->bf16 via LDS (29cyc) + STS right after the
// data-ready barrier. Accumulation order per element identical to R15/R16
// (chunk asc, ks asc, limb hi->lo) -> bit-identical output.
// ---------------------------------------------------------------------------
#define KC          64
#define A_BYTES     (128 * 144)               // 18432  (A bf16 tile)
#define B_BYTES     (128 * 144)               // 18432  per limb
#define BITS_OFF    (A_BYTES + 2 * B_BYTES)   // 55296
#define BITS_BYTES  1024                      // 128 rows x 2 words
#define BUF_BYTES   (BITS_OFF + BITS_BYTES)   // 56320
#define GSM_TOTAL   (2 * BUF_BYTES)           // 112640  (2 CTAs/SM: 225,280)

// Async stage of chunk data (bits + B limbs) into buffer p. No LDG stalls.
__device__ __forceinline__ void stage_async(uint32_t sb, int p, int t,
                                            size_t m0, int n0, int k0, int tid) {
    uint32_t base = sb + (uint32_t)p * BUF_BYTES;
    // A spike bits: 128 rows x 2 words; thread: row = tid>>1, half = tid&1.
    {
        int row = tid >> 1, half = tid & 1;
        CP_ASYNC4(base + BITS_OFF + (uint32_t)(row * 2 + half) * 4,
                  g_spk1b + ((size_t)t * BATCH + m0 + row) * 32 + (k0 >> 5) + half);
    }
    // B hi & lo: 128 rows x 64 bf16 each = 1024 x 16B chunks per limb
    #pragma unroll
    for (int limb = 0; limb < 2; limb++) {
        const __nv_bfloat16* W = limb ? g_w2lo : g_w2hi;
        uint32_t bb = base + A_BYTES + (uint32_t)limb * B_BYTES;
        #pragma unroll
        for (int it = 0; it < 4; it++) {
            int idx = tid + it * 256;
            int row = idx >> 3, j = idx & 7;
            CP_ASYNC16(bb + row * 144 + j * 16,
                       W + (size_t)(n0 + row) * H1 + k0 + j * 8);
        }
    }
}

// Expand bits (already in smem) -> bf16 A tile in buffer p. LDS + 4x STS.128.
__device__ __forceinline__ void expand_a(char* smem, int p, int tid) {
    char* bufc = smem + (size_t)p * BUF_BYTES;
    int row = tid >> 1, half = tid & 1;
    uint32_t u = *(const uint32_t*)(bufc + BITS_OFF + (row * 2 + half) * 4);
    char* dst = bufc + row * 144 + half * 64;
    #pragma unroll
    for (int q4 = 0; q4 < 4; q4++) {
        uint4 v;
        uint32_t s = u >> (q4 * 8);
        v.x = ((s      ) & 1) * 0x3F80u | ((s >> 1) & 1) * 0x3F800000u;
        v.y = ((s >> 2) & 1) * 0x3F80u | ((s >> 3) & 1) * 0x3F800000u;
        v.z = ((s >> 4) & 1) * 0x3F80u | ((s >> 5) & 1) * 0x3F800000u;
        v.w = ((s >> 6) & 1) * 0x3F80u | ((s >> 7) & 1) * 0x3F800000u;
        *(uint4*)(dst + q4 * 16) = v;
    }
}

__global__ void __launch_bounds__(256, 2) k2_gemm2(const float* __restrict__ b2) {
    extern __shared__ char smem[];
    uint32_t sb = smem_to_u32(smem);
    int tid  = threadIdx.x;
    int lane = tid & 31;
    int wid  = tid >> 5;
    int wm   = wid >> 2;          // 0..1  (M)
    int wn   = wid & 3;           // 0..3  (N)

    size_t m0 = (size_t)(blockIdx.x >> 2) * 128;
    int    n0 = (blockIdx.x & 3) * 128;
    int    ng = n0 + wn * 32;

    // b2 fragment (8 cols owned by this thread), loaded once
    float b2r[8];
    #pragma unroll
    for (int nf = 0; nf < 4; nf++) {
        int c = ng + nf * 8 + (lane & 3) * 2;
        b2r[nf * 2 + 0] = b2[c];
        b2r[nf * 2 + 1] = b2[c + 1];
    }

    float acc[4][4][4];
    #pragma unroll
    for (int i = 0; i < 4; i++)
        #pragma unroll
        for (int j = 0; j < 4; j++)
            #pragma unroll
            for (int q = 0; q < 4; q++) acc[i][j][q] = 0.0f;

    // Prologue: async-stage chunk 0
    stage_async(sb, 0, 0, m0, n0, 0, tid);
    CP_COMMIT();

    // 400 fused chunks: c -> (t = c>>4, k0 = (c&15)*KC)
    #pragma unroll 1
    for (int c = 0; c < 400; c++) {
        int p = c & 1;
        CP_WAIT0();               // chunk c's bits + B complete (this thread)
        __syncthreads();          // ... and visible CTA-wide

        expand_a(smem, p, tid);   // LDS bits -> STS bf16 A tile (fast)

        if (c < 399) {            // prefetch chunk c+1 (overlaps MMA phase)
            int nc = c + 1;
            stage_async(sb, p ^ 1, nc >> 4, m0, n0, (nc & 15) * KC, tid);
            CP_COMMIT();
        }
        __syncthreads();          // A tile visible to all warps

        uint32_t bufb  = sb + (uint32_t)p * BUF_BYTES;
        uint32_t aBase = bufb + (uint32_t)(wm * 64 + (lane & 15)) * 144 + (uint32_t)((lane >> 4) * 16);
        uint32_t bRow  = (uint32_t)(wn * 32 + (lane & 15)) * 144 + (uint32_t)((lane >> 4) * 16);
        uint32_t bH    = bufb + A_BYTES + bRow;
        uint32_t bL    = bH + B_BYTES;

        #pragma unroll
        for (int ks = 0; ks < 4; ks++) {
            uint32_t a[4][4];
            #pragma unroll
            for (int mt = 0; mt < 4; mt++)
                LDMX4(a[mt], aBase + mt * 2304 + ks * 32);
            #pragma unroll
            for (int limb = 0; limb < 2; limb++) {
                uint32_t bb = limb ? bL : bH;
                #pragma unroll
                for (int jb = 0; jb < 2; jb++) {
                    uint32_t b[4];
                    LDMX4(b, bb + jb * 2304 + ks * 32);
                    #pragma unroll
                    for (int mt = 0; mt < 4; mt++) {
                        MMA_BF16(acc[mt][jb * 2 + 0], a[mt], b[0], b[2]);
                        MMA_BF16(acc[mt][jb * 2 + 1], a[mt], b[1], b[3]);
                    }
                }
            }
        }

        // --- End of timestep: fused epilogue (LIF2 on g_mem2, spk2 bits) ---
        if ((c & 15) == 15) {
            int t = c >> 4;
            bool first = (t == 0);
            size_t mgw = m0 + (size_t)wm * 64;
            #pragma unroll
            for (int mt = 0; mt < 4; mt++) {
                #pragma unroll
                for (int half = 0; half < 2; half++) {
                    size_t row = mgw + mt * 16 + (lane >> 2) + half * 8;
                    float* m2p = g_mem2 + row * H2;
                    uint32_t wbits = 0u;
                    #pragma unroll
                    for (int nf = 0; nf < 4; nf++) {
                        int cc = ng + nf * 8 + (lane & 3) * 2;
                        float a0 = __fadd_rn(acc[mt][nf][half * 2 + 0], b2r[nf * 2 + 0]);
                        float a1 = __fadd_rn(acc[mt][nf][half * 2 + 1], b2r[nf * 2 + 1]);
                        float mA, mB;
                        if (first) { mA = 0.0f; mB = 0.0f; }
                        else { float2 mv = *(float2*)(m2p + cc); mA = mv.x; mB = mv.y; }
                        float sA, sB;
                        lif_step(mA, a0, sA);
                        lif_step(mB, a1, sB);
                        *(float2*)(m2p + cc) = make_float2(mA, mB);
                        int bp = nf * 8 + (lane & 3) * 2;
                        wbits |= ((sA > 0.5f) ? 1u : 0u) << bp
                               | ((sB > 0.5f) ? 1u : 0u) << (bp + 1);
                    }
                    wbits |= __shfl_xor_sync(0xffffffffu, wbits, 1);
                    wbits |= __shfl_xor_sync(0xffffffffu, wbits, 2);
                    if ((lane & 3) == 0)
                        g_spk2b[((size_t)t * BATCH + row) * 16 + (ng >> 5)] = wbits;
                }
            }
            // reset accumulators for next timestep
            #pragma unroll
            for (int i = 0; i < 4; i++)
                #pragma unroll
                for (int j = 0; j < 4; j++)
                    #pragma unroll
                    for (int q = 0; q < 4; q++) acc[i][j][q] = 0.0f;
        }
    }
}

// ---------------------------------------------------------------------------
// Kernel 3: layer-3 recurrence + output from spk2 bits. One warp per batch row.
// ---------------------------------------------------------------------------
__global__ void __launch_bounds__(256) k3_output(const float* __restrict__ W3,
                                                 const float* __restrict__ b3,
                                                 float* __restrict__ out) {
    int warp = (blockIdx.x * 256 + threadIdx.x) >> 5;
    int lane = threadIdx.x & 31;
    if (warp >= BATCH) return;
    size_t b = (size_t)warp;

    float w3r[16];
    #pragma unroll
    for (int j = 0; j < 16; j++) w3r[j] = W3[lane * 16 + j];
    float bb3 = b3[0];
    float mem3 = 0.0f, accm = 0.0f;

    for (int t = 0; t < TSTEPS; t++) {
        uint32_t word = g_spk2b[((size_t)t * BATCH + b) * 16 + (lane >> 1)];
        uint32_t half = (word >> ((lane & 1) * 16)) & 0xFFFFu;
        float cs = 0.0f;
        #pragma unroll
        for (int j = 0; j < 16; j++)
            if ((half >> j) & 1) cs += w3r[j];
        #pragma unroll
        for (int o = 16; o > 0; o >>= 1)
            cs += __shfl_xor_sync(0xffffffffu, cs, o);
        float cur3 = __fadd_rn(cs, bb3);
        float r3 = (mem3 > 1.0f) ? 1.0f : 0.0f;
        mem3 = __fsub_rn(__fadd_rn(__fmul_rn(BETA, mem3), cur3), r3);
        accm += mem3;
    }
    if (lane == 0) {
        float m = accm / 25.0f;
        out[warp] = 1.0f / (1.0f + expf(-m));
    }
}

// ---------------------------------------------------------------------------
// Launch
// ---------------------------------------------------------------------------
extern "C" void kernel_launch(void* const* d_in, const int* in_sizes, int n_in,
                              void* d_out, int out_size) {
    const float* x  = (const float*)d_in[0];
    const float* W1 = (const float*)d_in[1];
    const float* b1 = (const float*)d_in[2];
    const float* W2 = (const float*)d_in[3];
    const float* b2 = (const float*)d_in[4];
    const float* W3 = (const float*)d_in[5];
    const float* b3 = (const float*)d_in[6];
    float* out = (float*)d_out;

    cudaFuncSetAttribute(k2_gemm2, cudaFuncAttributeMaxDynamicSharedMemorySize, GSM_TOTAL);

    k_prep_w2<<<(H1 * H2) / 256, 256>>>(W2);
    k0_gemm1<<<(BATCH / 64) * (H1 / 64), 256>>>(x, W1, b1);
    k1_spikes<<<(BATCH * 32) / 8, 256>>>();
    k2_gemm2<<<(BATCH / 128) * (H2 / 128), 256, GSM_TOTAL>>>(b2);
    k3_output<<<(BATCH * 32) / 256, 256>>>(W3, b3, out);
}